// round 12
// baseline (speedup 1.0000x reference)
#include <cuda_runtime.h>
#include <cstdint>
#include <math.h>

#define BB 2
#define SS 2048
#define EE 1024
#define HH 16
#define DHH 64
#define MM (BB*SS)

// Scratch (no cudaMalloc allowed)
__device__ float g_q[BB*HH*SS*DHH];
__device__ float g_k[BB*HH*SS*DHH];
__device__ float g_v[BB*HH*SS*DHH];
__device__ float g_attn[BB*SS*EE];
__device__ float g_wt[4*EE*EE];      // transposed + tf32-rounded weights [N][K]

__device__ __forceinline__ float tf32r(float x) {
    float y;
    asm("cvt.rna.tf32.f32 %0, %1;" : "=f"(y) : "f"(x));
    return y;
}

// m16n8k8 tf32 mma.sync (standard sm_80+ PTX — works on .target sm_103)
#define MMA_TF32(c, a, b) \
    asm volatile("mma.sync.aligned.m16n8k8.row.col.f32.tf32.tf32.f32 " \
        "{%0,%1,%2,%3}, {%4,%5,%6,%7}, {%8,%9}, {%0,%1,%2,%3};" \
        : "+f"((c)[0]), "+f"((c)[1]), "+f"((c)[2]), "+f"((c)[3]) \
        : "r"(__float_as_uint((a)[0])), "r"(__float_as_uint((a)[1])), \
          "r"(__float_as_uint((a)[2])), "r"(__float_as_uint((a)[3])), \
          "r"(__float_as_uint((b)[0])), "r"(__float_as_uint((b)[1])))

// ---------------------------------------------------------------------------
// Merged weight transpose + tf32 rounding: z selects Wq/Wk/Wv/Wo
// ---------------------------------------------------------------------------
__global__ __launch_bounds__(256) void transpose4_kernel(
    const float* __restrict__ Wq, const float* __restrict__ Wk,
    const float* __restrict__ Wv, const float* __restrict__ Wo)
{
    __shared__ float t[32][33];
    const int z = blockIdx.z;
    const float* W = (z == 0) ? Wq : (z == 1) ? Wk : (z == 2) ? Wv : Wo;
    float* Wt = g_wt + (size_t)z * EE * EE;
    const int bx = blockIdx.x * 32;
    const int by = blockIdx.y * 32;
    const int x = threadIdx.x, y = threadIdx.y;
    #pragma unroll
    for (int r = 0; r < 4; r++)
        t[y + r * 8][x] = W[(size_t)(by + y + r * 8) * EE + bx + x];
    __syncthreads();
    #pragma unroll
    for (int r = 0; r < 4; r++)
        Wt[(size_t)(bx + y + r * 8) * EE + by + x] = tf32r(t[x][y + r * 8]);
}

// ---------------------------------------------------------------------------
// HMMA tf32 GEMM body: block 128x128, 8 warps (2m x 4n), warp tile 64x32,
// k-chunk 16, double-buffered smem (pad-20 rows), occupancy 2.
// ---------------------------------------------------------------------------
#define TK 16
#define NCH (EE / TK)                        // 64
#define ASZ (128 * 20)
#define BSZ (128 * 20)
#define GEMM_SMEM ((2 * ASZ + 2 * BSZ) * 4)  // 40960 B
#define AS(bf, r, c) sm[(bf) * ASZ + (r) * 20 + (c)]
#define BS(bf, r, c) sm[2 * ASZ + (bf) * BSZ + (r) * 20 + (c)]

template <int SPLIT>
__device__ __forceinline__ void gemm_body(
    const float* __restrict__ X, const float* __restrict__ Wt,
    const float* __restrict__ bias, float* __restrict__ out)
{
    extern __shared__ float sm[];
    const int tid = threadIdx.x;
    const int wid = tid >> 5, lane = tid & 31;
    const int g = lane >> 2, t4 = lane & 3;
    const int wm = wid >> 2, wn = wid & 3;
    const int n0 = blockIdx.x * 128;
    const int m0 = blockIdx.y * 128;

    const int lrow = tid >> 2;
    const int lc4  = tid & 3;

    float c[4][4][4];
    #pragma unroll
    for (int mi = 0; mi < 4; mi++)
        #pragma unroll
        for (int ni = 0; ni < 4; ni++)
            #pragma unroll
            for (int e = 0; e < 4; e++) c[mi][ni][e] = 0.f;

    float4 Ar[2], Br[2];

    #pragma unroll
    for (int r = 0; r < 2; r++) {
        Ar[r] = *(const float4*)(X  + (size_t)(m0 + lrow + r * 64) * EE + lc4 * 4);
        Br[r] = *(const float4*)(Wt + (size_t)(n0 + lrow + r * 64) * EE + lc4 * 4);
    }
    #pragma unroll
    for (int r = 0; r < 2; r++) {
        float4 v = Ar[r];
        v.x = tf32r(v.x); v.y = tf32r(v.y); v.z = tf32r(v.z); v.w = tf32r(v.w);
        *(float4*)&AS(0, lrow + r * 64, lc4 * 4) = v;
        *(float4*)&BS(0, lrow + r * 64, lc4 * 4) = Br[r];
    }
    __syncthreads();
    #pragma unroll
    for (int r = 0; r < 2; r++) {
        Ar[r] = *(const float4*)(X  + (size_t)(m0 + lrow + r * 64) * EE + TK + lc4 * 4);
        Br[r] = *(const float4*)(Wt + (size_t)(n0 + lrow + r * 64) * EE + TK + lc4 * 4);
    }

    for (int t = 0; t < NCH; t++) {
        const int buf = t & 1;
        if (t + 1 < NCH) {
            #pragma unroll
            for (int r = 0; r < 2; r++) {
                float4 v = Ar[r];
                v.x = tf32r(v.x); v.y = tf32r(v.y); v.z = tf32r(v.z); v.w = tf32r(v.w);
                *(float4*)&AS(buf ^ 1, lrow + r * 64, lc4 * 4) = v;
                *(float4*)&BS(buf ^ 1, lrow + r * 64, lc4 * 4) = Br[r];
            }
        }
        if (t + 2 < NCH) {
            const int k0 = (t + 2) * TK;
            #pragma unroll
            for (int r = 0; r < 2; r++) {
                Ar[r] = *(const float4*)(X  + (size_t)(m0 + lrow + r * 64) * EE + k0 + lc4 * 4);
                Br[r] = *(const float4*)(Wt + (size_t)(n0 + lrow + r * 64) * EE + k0 + lc4 * 4);
            }
        }
        #pragma unroll
        for (int kk = 0; kk < TK; kk += 8) {
            float a[4][4], b[4][2];
            #pragma unroll
            for (int mi = 0; mi < 4; mi++) {
                const int row = wm * 64 + mi * 16;
                a[mi][0] = AS(buf, row + g, kk + t4);
                a[mi][1] = AS(buf, row + g + 8, kk + t4);
                a[mi][2] = AS(buf, row + g, kk + t4 + 4);
                a[mi][3] = AS(buf, row + g + 8, kk + t4 + 4);
            }
            #pragma unroll
            for (int ni = 0; ni < 4; ni++) {
                const int col = wn * 32 + ni * 8 + g;
                b[ni][0] = BS(buf, col, kk + t4);
                b[ni][1] = BS(buf, col, kk + t4 + 4);
            }
            #pragma unroll
            for (int mi = 0; mi < 4; mi++)
                #pragma unroll
                for (int ni = 0; ni < 4; ni++)
                    MMA_TF32(c[mi][ni], a[mi], b[ni]);
        }
        __syncthreads();
    }

    #pragma unroll
    for (int mi = 0; mi < 4; mi++) {
        #pragma unroll
        for (int ni = 0; ni < 4; ni++) {
            const int r0 = m0 + wm * 64 + mi * 16 + g;
            const int cb = n0 + wn * 32 + ni * 8 + t4 * 2;
            const float bx = bias[cb], by = bias[cb + 1];
            #pragma unroll
            for (int half = 0; half < 2; half++) {
                const int r = r0 + half * 8;
                float2 v;
                v.x = c[mi][ni][half * 2 + 0] + bx;
                v.y = c[mi][ni][half * 2 + 1] + by;
                if (SPLIT) {
                    const int bbi = r >> 11, s = r & (SS - 1);
                    const int h = cb >> 6, d = cb & 63;
                    *(float2*)(out + ((size_t)(bbi * HH + h) * SS + s) * DHH + d) = v;
                } else {
                    *(float2*)(out + (size_t)r * EE + cb) = v;
                }
            }
        }
    }
}

__global__ __launch_bounds__(256, 2) void proj_gemm_kernel(
    const float* __restrict__ X, const float* __restrict__ Wt,
    const float* __restrict__ bias, float* __restrict__ out)
{
    gemm_body<1>(X, Wt, bias, out);
}

__global__ __launch_bounds__(256, 2) void o_gemm_kernel(
    const float* __restrict__ bias, float* __restrict__ out)
{
    gemm_body<0>(g_attn, g_wt + (size_t)3 * EE * EE, bias, out);
}

// ---------------------------------------------------------------------------
// MMA flash attention (exact R6-validated version): CTA = 128 q-rows; 64-key
// tiles; smem online softmax; NO register cap (occupancy 1, no spills).
// ---------------------------------------------------------------------------
#define AQ(r, cc)  sm[(r) * 68 + (cc)]
#define AK(r, cc)  sm[8704 + (r) * 68 + (cc)]
#define AV(d, kk)  sm[13056 + (d) * 68 + (kk)]
#define AP(r, cc)  sm[17408 + (r) * 68 + (cc)]
#define AM(r)      sm[26112 + (r)]
#define AL(r)      sm[26240 + (r)]
#define ASC(r)     sm[26368 + (r)]
#define AMK(kk)    ((int*)(sm + 26496))[(kk)]
#define ATTN_SMEM  (26560 * 4)

__global__ __launch_bounds__(256) void attn_mma_kernel(
    const int* __restrict__ mask, float* __restrict__ out)
{
    extern __shared__ float sm[];
    const int tid = threadIdx.x;
    const int wid = tid >> 5, lane = tid & 31;
    const int g = lane >> 2, t4 = lane & 3;
    const int wm = wid >> 2, wn = wid & 3;
    const int bb = blockIdx.z, hh = blockIdx.y;
    const int q0 = blockIdx.x * 128;

    const float* Q = g_q + ((size_t)(bb * HH + hh) * SS) * DHH;
    const float* K = g_k + ((size_t)(bb * HH + hh) * SS) * DHH;
    const float* V = g_v + ((size_t)(bb * HH + hh) * SS) * DHH;

    #pragma unroll
    for (int r = 0; r < 8; r++) {
        const int id = r * 256 + tid;
        const int row = id >> 4, c4 = id & 15;
        float4 v = *(const float4*)(Q + (size_t)(q0 + row) * DHH + c4 * 4);
        v.x = tf32r(v.x); v.y = tf32r(v.y); v.z = tf32r(v.z); v.w = tf32r(v.w);
        *(float4*)&AQ(row, c4 * 4) = v;
    }
    if (tid < 128) { AM(tid) = -1e30f; AL(tid) = 0.f; }

    float o[4][2][4];
    #pragma unroll
    for (int mi = 0; mi < 4; mi++)
        #pragma unroll
        for (int ni = 0; ni < 2; ni++)
            #pragma unroll
            for (int e = 0; e < 4; e++) o[mi][ni][e] = 0.f;
    __syncthreads();

    for (int kt = 0; kt < SS; kt += 64) {
        #pragma unroll
        for (int r = 0; r < 4; r++) {
            const int id = r * 256 + tid;
            const int key = id >> 4, c4 = id & 15;
            float4 kv = *(const float4*)(K + (size_t)(kt + key) * DHH + c4 * 4);
            kv.x = tf32r(kv.x); kv.y = tf32r(kv.y); kv.z = tf32r(kv.z); kv.w = tf32r(kv.w);
            *(float4*)&AK(key, c4 * 4) = kv;
            float4 vv = *(const float4*)(V + (size_t)(kt + key) * DHH + c4 * 4);
            AV(c4 * 4 + 0, key) = tf32r(vv.x);
            AV(c4 * 4 + 1, key) = tf32r(vv.y);
            AV(c4 * 4 + 2, key) = tf32r(vv.z);
            AV(c4 * 4 + 3, key) = tf32r(vv.w);
        }
        if (tid < 64) AMK(tid) = mask[bb * SS + kt + tid];
        __syncthreads();

        float c[4][2][4];
        #pragma unroll
        for (int mi = 0; mi < 4; mi++)
            #pragma unroll
            for (int ni = 0; ni < 2; ni++)
                #pragma unroll
                for (int e = 0; e < 4; e++) c[mi][ni][e] = 0.f;

        #pragma unroll
        for (int kk = 0; kk < 64; kk += 8) {
            float a[4][4], b[2][2];
            #pragma unroll
            for (int mi = 0; mi < 4; mi++) {
                const int row = wm * 64 + mi * 16;
                a[mi][0] = AQ(row + g, kk + t4);
                a[mi][1] = AQ(row + g + 8, kk + t4);
                a[mi][2] = AQ(row + g, kk + t4 + 4);
                a[mi][3] = AQ(row + g + 8, kk + t4 + 4);
            }
            #pragma unroll
            for (int ni = 0; ni < 2; ni++) {
                const int col = wn * 16 + ni * 8 + g;
                b[ni][0] = AK(col, kk + t4);
                b[ni][1] = AK(col, kk + t4 + 4);
            }
            #pragma unroll
            for (int mi = 0; mi < 4; mi++)
                #pragma unroll
                for (int ni = 0; ni < 2; ni++)
                    MMA_TF32(c[mi][ni], a[mi], b[ni]);
        }

        #pragma unroll
        for (int mi = 0; mi < 4; mi++) {
            const int r0 = wm * 64 + mi * 16 + g;
            #pragma unroll
            for (int ni = 0; ni < 2; ni++) {
                const int cb = wn * 16 + ni * 8 + t4 * 2;
                const int mk0 = AMK(cb), mk1 = AMK(cb + 1);
                float v0 = c[mi][ni][0] * 0.125f, v1 = c[mi][ni][1] * 0.125f;
                float v2 = c[mi][ni][2] * 0.125f, v3 = c[mi][ni][3] * 0.125f;
                if (mk0 == 0) { v0 = -1e9f; v2 = -1e9f; }
                if (mk1 == 0) { v1 = -1e9f; v3 = -1e9f; }
                AP(r0, cb) = v0;     AP(r0, cb + 1) = v1;
                AP(r0 + 8, cb) = v2; AP(r0 + 8, cb + 1) = v3;
            }
        }
        __syncthreads();

        {
            const int rrow = tid >> 1, half = tid & 1;
            float vals[32];
            float tmax = -1e30f;
            #pragma unroll
            for (int cc = 0; cc < 32; cc++) {
                vals[cc] = AP(rrow, half * 32 + cc);
                tmax = fmaxf(tmax, vals[cc]);
            }
            tmax = fmaxf(tmax, __shfl_xor_sync(0xffffffffu, tmax, 1));
            const float m_old = AM(rrow);
            const float m_new = fmaxf(m_old, tmax);
            float tsum = 0.f;
            #pragma unroll
            for (int cc = 0; cc < 32; cc++) {
                float p = tf32r(__expf(vals[cc] - m_new));
                AP(rrow, half * 32 + cc) = p;
                tsum += p;
            }
            tsum += __shfl_xor_sync(0xffffffffu, tsum, 1);
            if (half == 0) {
                const float sc = __expf(m_old - m_new);
                AL(rrow) = AL(rrow) * sc + tsum;
                AM(rrow) = m_new;
                ASC(rrow) = sc;
            }
        }
        __syncthreads();

        #pragma unroll
        for (int mi = 0; mi < 4; mi++) {
            const int r0 = wm * 64 + mi * 16 + g;
            const float s0 = ASC(r0), s1 = ASC(r0 + 8);
            #pragma unroll
            for (int ni = 0; ni < 2; ni++) {
                o[mi][ni][0] *= s0; o[mi][ni][1] *= s0;
                o[mi][ni][2] *= s1; o[mi][ni][3] *= s1;
            }
        }

        #pragma unroll
        for (int kk = 0; kk < 64; kk += 8) {
            float a[4][4], b[2][2];
            #pragma unroll
            for (int mi = 0; mi < 4; mi++) {
                const int row = wm * 64 + mi * 16;
                a[mi][0] = AP(row + g, kk + t4);
                a[mi][1] = AP(row + g + 8, kk + t4);
                a[mi][2] = AP(row + g, kk + t4 + 4);
                a[mi][3] = AP(row + g + 8, kk + t4 + 4);
            }
            #pragma unroll
            for (int ni = 0; ni < 2; ni++) {
                const int col = wn * 16 + ni * 8 + g;
                b[ni][0] = AV(col, kk + t4);
                b[ni][1] = AV(col, kk + t4 + 4);
            }
            #pragma unroll
            for (int mi = 0; mi < 4; mi++)
                #pragma unroll
                for (int ni = 0; ni < 2; ni++)
                    MMA_TF32(o[mi][ni], a[mi], b[ni]);
        }
        __syncthreads();
    }

    #pragma unroll
    for (int mi = 0; mi < 4; mi++) {
        const int r0 = wm * 64 + mi * 16 + g;
        const float li0 = 1.0f / AL(r0), li1 = 1.0f / AL(r0 + 8);
        #pragma unroll
        for (int ni = 0; ni < 2; ni++) {
            const int cb = wn * 16 + ni * 8 + t4 * 2;
            float2 v;
            v.x = o[mi][ni][0] * li0; v.y = o[mi][ni][1] * li0;
            *(float2*)(out + (size_t)(bb * SS + q0 + r0) * EE + hh * DHH + cb) = v;
            v.x = o[mi][ni][2] * li1; v.y = o[mi][ni][3] * li1;
            *(float2*)(out + (size_t)(bb * SS + q0 + r0 + 8) * EE + hh * DHH + cb) = v;
        }
    }
}

// ---------------------------------------------------------------------------
extern "C" void kernel_launch(void* const* d_in, const int* in_sizes, int n_in,
                              void* d_out, int out_size)
{
    const float* query = (const float*)d_in[0];
    const float* key   = (const float*)d_in[1];
    const float* value = (const float*)d_in[2];
    const int*   mask  = (const int*)  d_in[3];
    const float* Wq = (const float*)d_in[4];
    const float* bq = (const float*)d_in[5];
    const float* Wk = (const float*)d_in[6];
    const float* bk = (const float*)d_in[7];
    const float* Wv = (const float*)d_in[8];
    const float* bv = (const float*)d_in[9];
    const float* Wo = (const float*)d_in[10];
    const float* bo = (const float*)d_in[11];
    float* out = (float*)d_out;

    float *gq, *gk, *gv, *ga, *gw;
    cudaGetSymbolAddress((void**)&gq, g_q);
    cudaGetSymbolAddress((void**)&gk, g_k);
    cudaGetSymbolAddress((void**)&gv, g_v);
    cudaGetSymbolAddress((void**)&ga, g_attn);
    cudaGetSymbolAddress((void**)&gw, g_wt);

    cudaFuncSetAttribute(attn_mma_kernel,
                         cudaFuncAttributeMaxDynamicSharedMemorySize, ATTN_SMEM);
    cudaFuncSetAttribute(proj_gemm_kernel,
                         cudaFuncAttributeMaxDynamicSharedMemorySize, GEMM_SMEM);
    cudaFuncSetAttribute(o_gemm_kernel,
                         cudaFuncAttributeMaxDynamicSharedMemorySize, GEMM_SMEM);

    dim3 tgrid(EE / 32, EE / 32, 4);
    dim3 tblk(32, 8);
    transpose4_kernel<<<tgrid, tblk>>>(Wq, Wk, Wv, Wo);

    dim3 ggrid(EE / 128, MM / 128);        // (8, 32) = 256 CTAs
    proj_gemm_kernel<<<ggrid, 256, GEMM_SMEM>>>(query, gw + 0 * (size_t)EE * EE, bq, gq);
    proj_gemm_kernel<<<ggrid, 256, GEMM_SMEM>>>(key,   gw + 1 * (size_t)EE * EE, bk, gk);
    proj_gemm_kernel<<<ggrid, 256, GEMM_SMEM>>>(value, gw + 2 * (size_t)EE * EE, bv, gv);

    dim3 agrid(SS / 128, HH, BB);          // (16, 16, 2)
    attn_mma_kernel<<<agrid, 256, ATTN_SMEM>>>(mask, ga);

    o_gemm_kernel<<<ggrid, 256, GEMM_SMEM>>>(bo, out);
}

// round 13
// speedup vs baseline: 1.0436x; 1.0436x over previous
#include <cuda_runtime.h>
#include <cstdint>
#include <math.h>

#define BB 2
#define SS 2048
#define EE 1024
#define HH 16
#define DHH 64
#define MM (BB*SS)

// Scratch (no cudaMalloc allowed)
__device__ float g_q[BB*HH*SS*DHH];
__device__ float g_k[BB*HH*SS*DHH];
__device__ float g_v[BB*HH*SS*DHH];
__device__ float g_attn[BB*SS*EE];
__device__ float g_wt[4*EE*EE];      // transposed + tf32-rounded weights [N][K]

__device__ __forceinline__ float tf32r(float x) {
    float y;
    asm("cvt.rna.tf32.f32 %0, %1;" : "=f"(y) : "f"(x));
    return y;
}

// m16n8k8 tf32 mma.sync (standard sm_80+ PTX — works on .target sm_103)
#define MMA_TF32(c, a, b) \
    asm volatile("mma.sync.aligned.m16n8k8.row.col.f32.tf32.tf32.f32 " \
        "{%0,%1,%2,%3}, {%4,%5,%6,%7}, {%8,%9}, {%0,%1,%2,%3};" \
        : "+f"((c)[0]), "+f"((c)[1]), "+f"((c)[2]), "+f"((c)[3]) \
        : "r"(__float_as_uint((a)[0])), "r"(__float_as_uint((a)[1])), \
          "r"(__float_as_uint((a)[2])), "r"(__float_as_uint((a)[3])), \
          "r"(__float_as_uint((b)[0])), "r"(__float_as_uint((b)[1])))

// ---------------------------------------------------------------------------
// Merged weight transpose + tf32 rounding
// ---------------------------------------------------------------------------
__global__ __launch_bounds__(256) void transpose4_kernel(
    const float* __restrict__ Wq, const float* __restrict__ Wk,
    const float* __restrict__ Wv, const float* __restrict__ Wo)
{
    __shared__ float t[32][33];
    const int z = blockIdx.z;
    const float* W = (z == 0) ? Wq : (z == 1) ? Wk : (z == 2) ? Wv : Wo;
    float* Wt = g_wt + (size_t)z * EE * EE;
    const int bx = blockIdx.x * 32;
    const int by = blockIdx.y * 32;
    const int x = threadIdx.x, y = threadIdx.y;
    #pragma unroll
    for (int r = 0; r < 4; r++)
        t[y + r * 8][x] = W[(size_t)(by + y + r * 8) * EE + bx + x];
    __syncthreads();
    #pragma unroll
    for (int r = 0; r < 4; r++)
        Wt[(size_t)(bx + y + r * 8) * EE + by + x] = tf32r(t[x][y + r * 8]);
}

// ---------------------------------------------------------------------------
// HMMA tf32 GEMM (validated occ-2 version, unchanged from R11/R12)
// ---------------------------------------------------------------------------
#define TK 16
#define NCH (EE / TK)
#define ASZ (128 * 20)
#define BSZ (128 * 20)
#define GEMM_SMEM ((2 * ASZ + 2 * BSZ) * 4)
#define AS(bf, r, c) sm[(bf) * ASZ + (r) * 20 + (c)]
#define BS(bf, r, c) sm[2 * ASZ + (bf) * BSZ + (r) * 20 + (c)]

template <int SPLIT>
__device__ __forceinline__ void gemm_body(
    const float* __restrict__ X, const float* __restrict__ Wt,
    const float* __restrict__ bias, float* __restrict__ out)
{
    extern __shared__ float sm[];
    const int tid = threadIdx.x;
    const int wid = tid >> 5, lane = tid & 31;
    const int g = lane >> 2, t4 = lane & 3;
    const int wm = wid >> 2, wn = wid & 3;
    const int n0 = blockIdx.x * 128;
    const int m0 = blockIdx.y * 128;

    const int lrow = tid >> 2;
    const int lc4  = tid & 3;

    float c[4][4][4];
    #pragma unroll
    for (int mi = 0; mi < 4; mi++)
        #pragma unroll
        for (int ni = 0; ni < 4; ni++)
            #pragma unroll
            for (int e = 0; e < 4; e++) c[mi][ni][e] = 0.f;

    float4 Ar[2], Br[2];

    #pragma unroll
    for (int r = 0; r < 2; r++) {
        Ar[r] = *(const float4*)(X  + (size_t)(m0 + lrow + r * 64) * EE + lc4 * 4);
        Br[r] = *(const float4*)(Wt + (size_t)(n0 + lrow + r * 64) * EE + lc4 * 4);
    }
    #pragma unroll
    for (int r = 0; r < 2; r++) {
        float4 v = Ar[r];
        v.x = tf32r(v.x); v.y = tf32r(v.y); v.z = tf32r(v.z); v.w = tf32r(v.w);
        *(float4*)&AS(0, lrow + r * 64, lc4 * 4) = v;
        *(float4*)&BS(0, lrow + r * 64, lc4 * 4) = Br[r];
    }
    __syncthreads();
    #pragma unroll
    for (int r = 0; r < 2; r++) {
        Ar[r] = *(const float4*)(X  + (size_t)(m0 + lrow + r * 64) * EE + TK + lc4 * 4);
        Br[r] = *(const float4*)(Wt + (size_t)(n0 + lrow + r * 64) * EE + TK + lc4 * 4);
    }

    for (int t = 0; t < NCH; t++) {
        const int buf = t & 1;
        if (t + 1 < NCH) {
            #pragma unroll
            for (int r = 0; r < 2; r++) {
                float4 v = Ar[r];
                v.x = tf32r(v.x); v.y = tf32r(v.y); v.z = tf32r(v.z); v.w = tf32r(v.w);
                *(float4*)&AS(buf ^ 1, lrow + r * 64, lc4 * 4) = v;
                *(float4*)&BS(buf ^ 1, lrow + r * 64, lc4 * 4) = Br[r];
            }
        }
        if (t + 2 < NCH) {
            const int k0 = (t + 2) * TK;
            #pragma unroll
            for (int r = 0; r < 2; r++) {
                Ar[r] = *(const float4*)(X  + (size_t)(m0 + lrow + r * 64) * EE + k0 + lc4 * 4);
                Br[r] = *(const float4*)(Wt + (size_t)(n0 + lrow + r * 64) * EE + k0 + lc4 * 4);
            }
        }
        #pragma unroll
        for (int kk = 0; kk < TK; kk += 8) {
            float a[4][4], b[4][2];
            #pragma unroll
            for (int mi = 0; mi < 4; mi++) {
                const int row = wm * 64 + mi * 16;
                a[mi][0] = AS(buf, row + g, kk + t4);
                a[mi][1] = AS(buf, row + g + 8, kk + t4);
                a[mi][2] = AS(buf, row + g, kk + t4 + 4);
                a[mi][3] = AS(buf, row + g + 8, kk + t4 + 4);
            }
            #pragma unroll
            for (int ni = 0; ni < 4; ni++) {
                const int col = wn * 32 + ni * 8 + g;
                b[ni][0] = BS(buf, col, kk + t4);
                b[ni][1] = BS(buf, col, kk + t4 + 4);
            }
            #pragma unroll
            for (int mi = 0; mi < 4; mi++)
                #pragma unroll
                for (int ni = 0; ni < 4; ni++)
                    MMA_TF32(c[mi][ni], a[mi], b[ni]);
        }
        __syncthreads();
    }

    #pragma unroll
    for (int mi = 0; mi < 4; mi++) {
        #pragma unroll
        for (int ni = 0; ni < 4; ni++) {
            const int r0 = m0 + wm * 64 + mi * 16 + g;
            const int cb = n0 + wn * 32 + ni * 8 + t4 * 2;
            const float bx = bias[cb], by = bias[cb + 1];
            #pragma unroll
            for (int half = 0; half < 2; half++) {
                const int r = r0 + half * 8;
                float2 v;
                v.x = c[mi][ni][half * 2 + 0] + bx;
                v.y = c[mi][ni][half * 2 + 1] + by;
                if (SPLIT) {
                    const int bbi = r >> 11, s = r & (SS - 1);
                    const int h = cb >> 6, d = cb & 63;
                    *(float2*)(out + ((size_t)(bbi * HH + h) * SS + s) * DHH + d) = v;
                } else {
                    *(float2*)(out + (size_t)r * EE + cb) = v;
                }
            }
        }
    }
}

__global__ __launch_bounds__(256, 2) void proj_gemm_kernel(
    const float* __restrict__ X, const float* __restrict__ Wt,
    const float* __restrict__ bias, float* __restrict__ out)
{
    gemm_body<1>(X, Wt, bias, out);
}

__global__ __launch_bounds__(256, 2) void o_gemm_kernel(
    const float* __restrict__ bias, float* __restrict__ out)
{
    gemm_body<0>(g_attn, g_wt + (size_t)3 * EE * EE, bias, out);
}

// ---------------------------------------------------------------------------
// MMA flash attention: 128 q-rows x 128-KEY tiles (16 iterations),
// register softmax (R11-validated pattern). ~177KB smem, occ 1.
// ---------------------------------------------------------------------------
#define AQ(r, cc)  sm[(r) * 68 + (cc)]
#define AK(r, cc)  sm[8704 + (r) * 68 + (cc)]
#define AV(d, kk)  sm[17408 + (d) * 132 + (kk)]
#define AP(r, cc)  sm[25856 + (r) * 132 + (cc)]
#define AM(r)      sm[42752 + (r)]
#define AL(r)      sm[42880 + (r)]
#define ASC(r)     sm[43008 + (r)]
#define AMK(kk)    ((int*)(sm + 43136))[(kk)]
#define PMX(w, r)  sm[43264 + (w) * 128 + (r)]
#define PSM(w, r)  sm[43776 + (w) * 128 + (r)]
#define ATTN_SMEM  (44288 * 4)

__global__ __launch_bounds__(256) void attn_mma_kernel(
    const int* __restrict__ mask, float* __restrict__ out)
{
    extern __shared__ float sm[];
    const int tid = threadIdx.x;
    const int wid = tid >> 5, lane = tid & 31;
    const int g = lane >> 2, t4 = lane & 3;
    const int wm = wid >> 2, wn = wid & 3;
    const int bb = blockIdx.z, hh = blockIdx.y;
    const int q0 = blockIdx.x * 128;

    const float* Q = g_q + ((size_t)(bb * HH + hh) * SS) * DHH;
    const float* K = g_k + ((size_t)(bb * HH + hh) * SS) * DHH;
    const float* V = g_v + ((size_t)(bb * HH + hh) * SS) * DHH;

    #pragma unroll
    for (int r = 0; r < 8; r++) {
        const int id = r * 256 + tid;
        const int row = id >> 4, c4 = id & 15;
        float4 v = *(const float4*)(Q + (size_t)(q0 + row) * DHH + c4 * 4);
        v.x = tf32r(v.x); v.y = tf32r(v.y); v.z = tf32r(v.z); v.w = tf32r(v.w);
        *(float4*)&AQ(row, c4 * 4) = v;
    }
    if (tid < 128) { AM(tid) = -1e30f; AL(tid) = 0.f; }

    float o[4][2][4];
    #pragma unroll
    for (int mi = 0; mi < 4; mi++)
        #pragma unroll
        for (int ni = 0; ni < 2; ni++)
            #pragma unroll
            for (int e = 0; e < 4; e++) o[mi][ni][e] = 0.f;
    __syncthreads();

    for (int kt = 0; kt < SS; kt += 128) {
        // load 128 keys of K (row-major) and V (transposed [d][key])
        #pragma unroll
        for (int r = 0; r < 8; r++) {
            const int id = r * 256 + tid;
            const int key = id >> 4, c4 = id & 15;
            float4 kv = *(const float4*)(K + (size_t)(kt + key) * DHH + c4 * 4);
            kv.x = tf32r(kv.x); kv.y = tf32r(kv.y); kv.z = tf32r(kv.z); kv.w = tf32r(kv.w);
            *(float4*)&AK(key, c4 * 4) = kv;
            float4 vv = *(const float4*)(V + (size_t)(kt + key) * DHH + c4 * 4);
            AV(c4 * 4 + 0, key) = tf32r(vv.x);
            AV(c4 * 4 + 1, key) = tf32r(vv.y);
            AV(c4 * 4 + 2, key) = tf32r(vv.z);
            AV(c4 * 4 + 3, key) = tf32r(vv.w);
        }
        if (tid < 128) AMK(tid) = mask[bb * SS + kt + tid];
        __syncthreads();

        // ---- scores = Q @ K^T : 128 x 128, warp tile 64 x 32 keys ----
        float c[4][4][4];
        #pragma unroll
        for (int mi = 0; mi < 4; mi++)
            #pragma unroll
            for (int ni = 0; ni < 4; ni++)
                #pragma unroll
                for (int e = 0; e < 4; e++) c[mi][ni][e] = 0.f;

        #pragma unroll
        for (int kk = 0; kk < 64; kk += 8) {
            float a[4][4], b[4][2];
            #pragma unroll
            for (int mi = 0; mi < 4; mi++) {
                const int row = wm * 64 + mi * 16;
                a[mi][0] = AQ(row + g, kk + t4);
                a[mi][1] = AQ(row + g + 8, kk + t4);
                a[mi][2] = AQ(row + g, kk + t4 + 4);
                a[mi][3] = AQ(row + g + 8, kk + t4 + 4);
            }
            #pragma unroll
            for (int ni = 0; ni < 4; ni++) {
                const int col = wn * 32 + ni * 8 + g;
                b[ni][0] = AK(col, kk + t4);
                b[ni][1] = AK(col, kk + t4 + 4);
            }
            #pragma unroll
            for (int mi = 0; mi < 4; mi++)
                #pragma unroll
                for (int ni = 0; ni < 4; ni++)
                    MMA_TF32(c[mi][ni], a[mi], b[ni]);
        }

        // ---- register softmax: scale+mask, row-max partials ----
        int mk[4][2];
        #pragma unroll
        for (int ni = 0; ni < 4; ni++) {
            const int cb = wn * 32 + ni * 8 + t4 * 2;
            mk[ni][0] = AMK(cb); mk[ni][1] = AMK(cb + 1);
        }
        float rm0[4], rm1[4];
        #pragma unroll
        for (int mi = 0; mi < 4; mi++) {
            float m0 = -1e30f, m1 = -1e30f;
            #pragma unroll
            for (int ni = 0; ni < 4; ni++) {
                float v0 = c[mi][ni][0] * 0.125f, v1 = c[mi][ni][1] * 0.125f;
                float v2 = c[mi][ni][2] * 0.125f, v3 = c[mi][ni][3] * 0.125f;
                if (mk[ni][0] == 0) { v0 = -1e9f; v2 = -1e9f; }
                if (mk[ni][1] == 0) { v1 = -1e9f; v3 = -1e9f; }
                c[mi][ni][0] = v0; c[mi][ni][1] = v1;
                c[mi][ni][2] = v2; c[mi][ni][3] = v3;
                m0 = fmaxf(m0, fmaxf(v0, v1));
                m1 = fmaxf(m1, fmaxf(v2, v3));
            }
            m0 = fmaxf(m0, __shfl_xor_sync(0xffffffffu, m0, 1));
            m0 = fmaxf(m0, __shfl_xor_sync(0xffffffffu, m0, 2));
            m1 = fmaxf(m1, __shfl_xor_sync(0xffffffffu, m1, 1));
            m1 = fmaxf(m1, __shfl_xor_sync(0xffffffffu, m1, 2));
            rm0[mi] = m0; rm1[mi] = m1;
        }
        if (t4 == 0) {
            #pragma unroll
            for (int mi = 0; mi < 4; mi++) {
                const int r0 = wm * 64 + mi * 16 + g;
                PMX(wn, r0) = rm0[mi];
                PMX(wn, r0 + 8) = rm1[mi];
            }
        }
        __syncthreads();

        if (tid < 128) {
            const float mt = fmaxf(fmaxf(PMX(0, tid), PMX(1, tid)),
                                   fmaxf(PMX(2, tid), PMX(3, tid)));
            const float mo = AM(tid);
            const float mn = fmaxf(mo, mt);
            AM(tid) = mn;
            ASC(tid) = __expf(mo - mn);
        }
        __syncthreads();

        // ---- exp in regs, single Ps write, row-sum partials; rescale o ----
        #pragma unroll
        for (int mi = 0; mi < 4; mi++) {
            const int r0 = wm * 64 + mi * 16 + g;
            const float mn0 = AM(r0), mn1 = AM(r0 + 8);
            float s0 = 0.f, s1 = 0.f;
            #pragma unroll
            for (int ni = 0; ni < 4; ni++) {
                const int cb = wn * 32 + ni * 8 + t4 * 2;
                const float p0 = tf32r(__expf(c[mi][ni][0] - mn0));
                const float p1 = tf32r(__expf(c[mi][ni][1] - mn0));
                const float p2 = tf32r(__expf(c[mi][ni][2] - mn1));
                const float p3 = tf32r(__expf(c[mi][ni][3] - mn1));
                s0 += p0 + p1; s1 += p2 + p3;
                AP(r0, cb) = p0;     AP(r0, cb + 1) = p1;
                AP(r0 + 8, cb) = p2; AP(r0 + 8, cb + 1) = p3;
            }
            s0 += __shfl_xor_sync(0xffffffffu, s0, 1);
            s0 += __shfl_xor_sync(0xffffffffu, s0, 2);
            s1 += __shfl_xor_sync(0xffffffffu, s1, 1);
            s1 += __shfl_xor_sync(0xffffffffu, s1, 2);
            if (t4 == 0) { PSM(wn, r0) = s0; PSM(wn, r0 + 8) = s1; }
            const float sc0 = ASC(r0), sc1 = ASC(r0 + 8);
            #pragma unroll
            for (int ni = 0; ni < 2; ni++) {
                o[mi][ni][0] *= sc0; o[mi][ni][1] *= sc0;
                o[mi][ni][2] *= sc1; o[mi][ni][3] *= sc1;
            }
        }
        __syncthreads();

        if (tid < 128) {
            AL(tid) = AL(tid) * ASC(tid)
                    + PSM(0, tid) + PSM(1, tid) + PSM(2, tid) + PSM(3, tid);
        }

        // ---- O += P @ V : K-dim = 128 keys ----
        #pragma unroll
        for (int kk = 0; kk < 128; kk += 8) {
            float a[4][4], b[2][2];
            #pragma unroll
            for (int mi = 0; mi < 4; mi++) {
                const int row = wm * 64 + mi * 16;
                a[mi][0] = AP(row + g, kk + t4);
                a[mi][1] = AP(row + g + 8, kk + t4);
                a[mi][2] = AP(row + g, kk + t4 + 4);
                a[mi][3] = AP(row + g + 8, kk + t4 + 4);
            }
            #pragma unroll
            for (int ni = 0; ni < 2; ni++) {
                const int col = wn * 16 + ni * 8 + g;
                b[ni][0] = AV(col, kk + t4);
                b[ni][1] = AV(col, kk + t4 + 4);
            }
            #pragma unroll
            for (int mi = 0; mi < 4; mi++)
                #pragma unroll
                for (int ni = 0; ni < 2; ni++)
                    MMA_TF32(o[mi][ni], a[mi], b[ni]);
        }
        __syncthreads();
    }

    #pragma unroll
    for (int mi = 0; mi < 4; mi++) {
        const int r0 = wm * 64 + mi * 16 + g;
        const float li0 = 1.0f / AL(r0), li1 = 1.0f / AL(r0 + 8);
        #pragma unroll
        for (int ni = 0; ni < 2; ni++) {
            const int cb = wn * 16 + ni * 8 + t4 * 2;
            float2 v;
            v.x = o[mi][ni][0] * li0; v.y = o[mi][ni][1] * li0;
            *(float2*)(out + (size_t)(bb * SS + q0 + r0) * EE + hh * DHH + cb) = v;
            v.x = o[mi][ni][2] * li1; v.y = o[mi][ni][3] * li1;
            *(float2*)(out + (size_t)(bb * SS + q0 + r0 + 8) * EE + hh * DHH + cb) = v;
        }
    }
}

// ---------------------------------------------------------------------------
extern "C" void kernel_launch(void* const* d_in, const int* in_sizes, int n_in,
                              void* d_out, int out_size)
{
    const float* query = (const float*)d_in[0];
    const float* key   = (const float*)d_in[1];
    const float* value = (const float*)d_in[2];
    const int*   mask  = (const int*)  d_in[3];
    const float* Wq = (const float*)d_in[4];
    const float* bq = (const float*)d_in[5];
    const float* Wk = (const float*)d_in[6];
    const float* bk = (const float*)d_in[7];
    const float* Wv = (const float*)d_in[8];
    const float* bv = (const float*)d_in[9];
    const float* Wo = (const float*)d_in[10];
    const float* bo = (const float*)d_in[11];
    float* out = (float*)d_out;

    float *gq, *gk, *gv, *ga, *gw;
    cudaGetSymbolAddress((void**)&gq, g_q);
    cudaGetSymbolAddress((void**)&gk, g_k);
    cudaGetSymbolAddress((void**)&gv, g_v);
    cudaGetSymbolAddress((void**)&ga, g_attn);
    cudaGetSymbolAddress((void**)&gw, g_wt);

    cudaFuncSetAttribute(attn_mma_kernel,
                         cudaFuncAttributeMaxDynamicSharedMemorySize, ATTN_SMEM);
    cudaFuncSetAttribute(proj_gemm_kernel,
                         cudaFuncAttributeMaxDynamicSharedMemorySize, GEMM_SMEM);
    cudaFuncSetAttribute(o_gemm_kernel,
                         cudaFuncAttributeMaxDynamicSharedMemorySize, GEMM_SMEM);

    dim3 tgrid(EE / 32, EE / 32, 4);
    dim3 tblk(32, 8);
    transpose4_kernel<<<tgrid, tblk>>>(Wq, Wk, Wv, Wo);

    dim3 ggrid(EE / 128, MM / 128);        // (8, 32) = 256 CTAs
    proj_gemm_kernel<<<ggrid, 256, GEMM_SMEM>>>(query, gw + 0 * (size_t)EE * EE, bq, gq);
    proj_gemm_kernel<<<ggrid, 256, GEMM_SMEM>>>(key,   gw + 1 * (size_t)EE * EE, bk, gk);
    proj_gemm_kernel<<<ggrid, 256, GEMM_SMEM>>>(value, gw + 2 * (size_t)EE * EE, bv, gv);

    dim3 agrid(SS / 128, HH, BB);          // (16, 16, 2)
    attn_mma_kernel<<<agrid, 256, ATTN_SMEM>>>(mask, ga);

    o_gemm_kernel<<<ggrid, 256, GEMM_SMEM>>>(bo, out);
}

// round 14
// speedup vs baseline: 1.0611x; 1.0168x over previous
#include <cuda_runtime.h>
#include <cstdint>
#include <math.h>

#define BB 2
#define SS 2048
#define EE 1024
#define HH 16
#define DHH 64
#define MM (BB*SS)

// Scratch (no cudaMalloc allowed)
__device__ float g_q[BB*HH*SS*DHH];
__device__ float g_k[BB*HH*SS*DHH];
__device__ float g_v[BB*HH*SS*DHH];
__device__ float g_attn[BB*SS*EE];
__device__ float g_wt[4*EE*EE];      // transposed + tf32-rounded weights [N][K]
__device__ float g_in[3*(size_t)MM*EE];  // tf32-rounded activations q/k/v

__device__ __forceinline__ float tf32r(float x) {
    float y;
    asm("cvt.rna.tf32.f32 %0, %1;" : "=f"(y) : "f"(x));
    return y;
}
__device__ __forceinline__ uint32_t smem_u32(const void* p) {
    uint32_t a;
    asm("{ .reg .u64 t; cvta.to.shared.u64 t, %1; cvt.u32.u64 %0, t; }" : "=r"(a) : "l"(p));
    return a;
}

// m16n8k8 tf32 mma.sync (standard sm_80+ PTX — works on .target sm_103)
#define MMA_TF32(c, a, b) \
    asm volatile("mma.sync.aligned.m16n8k8.row.col.f32.tf32.tf32.f32 " \
        "{%0,%1,%2,%3}, {%4,%5,%6,%7}, {%8,%9}, {%0,%1,%2,%3};" \
        : "+f"((c)[0]), "+f"((c)[1]), "+f"((c)[2]), "+f"((c)[3]) \
        : "r"(__float_as_uint((a)[0])), "r"(__float_as_uint((a)[1])), \
          "r"(__float_as_uint((a)[2])), "r"(__float_as_uint((a)[3])), \
          "r"(__float_as_uint((b)[0])), "r"(__float_as_uint((b)[1])))

#define CP_ASYNC16(dst, src) \
    asm volatile("cp.async.cg.shared.global [%0], [%1], 16;" :: "r"(dst), "l"(src) : "memory")
#define CP_COMMIT() asm volatile("cp.async.commit_group;" ::: "memory")
#define CP_WAIT2()  asm volatile("cp.async.wait_group 2;" ::: "memory")

// ---------------------------------------------------------------------------
// Pre-round activations: g_in[z] = tf32r(input z)   (q, k, v)
// ---------------------------------------------------------------------------
__global__ __launch_bounds__(256) void round3_kernel(
    const float* __restrict__ q, const float* __restrict__ k,
    const float* __restrict__ v)
{
    const int z = blockIdx.y;
    const float* src = (z == 0) ? q : (z == 1) ? k : v;
    float* dst = g_in + (size_t)z * MM * EE;
    const size_t i = ((size_t)blockIdx.x * 256 + threadIdx.x) * 4;
    float4 x = *(const float4*)(src + i);
    x.x = tf32r(x.x); x.y = tf32r(x.y); x.z = tf32r(x.z); x.w = tf32r(x.w);
    *(float4*)(dst + i) = x;
}

// ---------------------------------------------------------------------------
// Merged weight transpose + tf32 rounding
// ---------------------------------------------------------------------------
__global__ __launch_bounds__(256) void transpose4_kernel(
    const float* __restrict__ Wq, const float* __restrict__ Wk,
    const float* __restrict__ Wv, const float* __restrict__ Wo)
{
    __shared__ float t[32][33];
    const int z = blockIdx.z;
    const float* W = (z == 0) ? Wq : (z == 1) ? Wk : (z == 2) ? Wv : Wo;
    float* Wt = g_wt + (size_t)z * EE * EE;
    const int bx = blockIdx.x * 32;
    const int by = blockIdx.y * 32;
    const int x = threadIdx.x, y = threadIdx.y;
    #pragma unroll
    for (int r = 0; r < 4; r++)
        t[y + r * 8][x] = W[(size_t)(by + y + r * 8) * EE + bx + x];
    __syncthreads();
    #pragma unroll
    for (int r = 0; r < 4; r++)
        Wt[(size_t)(bx + y + r * 8) * EE + by + x] = tf32r(t[x][y + r * 8]);
}

// ---------------------------------------------------------------------------
// HMMA tf32 GEMM: 128x128 tile, 8 warps (2m x 4n), warp 64x32, k-chunk 16.
// Both operands pre-rounded -> pure cp.async 4-stage pipeline, occupancy 2.
// ---------------------------------------------------------------------------
#define TK 16
#define NCH (EE / TK)                 // 64
#define STGF 5120                     // floats per stage (A 128*20 + B 128*20 /2... A=2560,B=2560)
#define GEMM_SMEM (4 * STGF * 4)      // 81920 B
#define AS(s, r, c) sm[(s) * STGF + (r) * 20 + (c)]
#define BS(s, r, c) sm[(s) * STGF + 2560 + (r) * 20 + (c)]

template <int SPLIT>
__device__ __forceinline__ void gemm_body(
    const float* __restrict__ X, const float* __restrict__ Wt,
    const float* __restrict__ bias, float* __restrict__ out)
{
    extern __shared__ float sm[];
    const uint32_t sb = smem_u32(sm);
    const int tid = threadIdx.x;
    const int wid = tid >> 5, lane = tid & 31;
    const int g = lane >> 2, t4 = lane & 3;
    const int wm = wid >> 2, wn = wid & 3;
    const int n0 = blockIdx.x * 128;
    const int m0 = blockIdx.y * 128;

    // loader: 2 ids per thread cover 128 rows x 4 float4s
    const int r0l = tid >> 2, c4l = tid & 3;   // id0: rows 0..63
    const float* Abase = X  + (size_t)m0 * EE;
    const float* Bbase = Wt + (size_t)n0 * EE;

    float c[4][4][4];
    #pragma unroll
    for (int mi = 0; mi < 4; mi++)
        #pragma unroll
        for (int ni = 0; ni < 4; ni++)
            #pragma unroll
            for (int e = 0; e < 4; e++) c[mi][ni][e] = 0.f;

    // prologue: stages 0..2
    #pragma unroll
    for (int s = 0; s < 3; s++) {
        const int k0 = s * TK;
        #pragma unroll
        for (int h = 0; h < 2; h++) {
            const int row = r0l + h * 64;
            const uint32_t da = sb + ((s * STGF + row * 20 + c4l * 4) << 2);
            CP_ASYNC16(da, Abase + (size_t)row * EE + k0 + c4l * 4);
            const uint32_t db = sb + ((s * STGF + 2560 + row * 20 + c4l * 4) << 2);
            CP_ASYNC16(db, Bbase + (size_t)row * EE + k0 + c4l * 4);
        }
        CP_COMMIT();
    }

    for (int t = 0; t < NCH; t++) {
        CP_WAIT2();
        __syncthreads();

        // issue stage t+3 into buffer (t+3)&3 (freed: all threads past compute t-1)
        if (t + 3 < NCH) {
            const int s = (t + 3) & 3;
            const int k0 = (t + 3) * TK;
            #pragma unroll
            for (int h = 0; h < 2; h++) {
                const int row = r0l + h * 64;
                const uint32_t da = sb + ((s * STGF + row * 20 + c4l * 4) << 2);
                CP_ASYNC16(da, Abase + (size_t)row * EE + k0 + c4l * 4);
                const uint32_t db = sb + ((s * STGF + 2560 + row * 20 + c4l * 4) << 2);
                CP_ASYNC16(db, Bbase + (size_t)row * EE + k0 + c4l * 4);
            }
        }
        CP_COMMIT();

        const int buf = t & 3;
        #pragma unroll
        for (int kk = 0; kk < TK; kk += 8) {
            float a[4][4], b[4][2];
            #pragma unroll
            for (int mi = 0; mi < 4; mi++) {
                const int row = wm * 64 + mi * 16;
                a[mi][0] = AS(buf, row + g, kk + t4);
                a[mi][1] = AS(buf, row + g + 8, kk + t4);
                a[mi][2] = AS(buf, row + g, kk + t4 + 4);
                a[mi][3] = AS(buf, row + g + 8, kk + t4 + 4);
            }
            #pragma unroll
            for (int ni = 0; ni < 4; ni++) {
                const int col = wn * 32 + ni * 8 + g;
                b[ni][0] = BS(buf, col, kk + t4);
                b[ni][1] = BS(buf, col, kk + t4 + 4);
            }
            #pragma unroll
            for (int mi = 0; mi < 4; mi++)
                #pragma unroll
                for (int ni = 0; ni < 4; ni++)
                    MMA_TF32(c[mi][ni], a[mi], b[ni]);
        }
        __syncthreads();
    }

    #pragma unroll
    for (int mi = 0; mi < 4; mi++) {
        #pragma unroll
        for (int ni = 0; ni < 4; ni++) {
            const int r0 = m0 + wm * 64 + mi * 16 + g;
            const int cb = n0 + wn * 32 + ni * 8 + t4 * 2;
            const float bx = bias[cb], by = bias[cb + 1];
            #pragma unroll
            for (int half = 0; half < 2; half++) {
                const int r = r0 + half * 8;
                float2 v;
                v.x = c[mi][ni][half * 2 + 0] + bx;
                v.y = c[mi][ni][half * 2 + 1] + by;
                if (SPLIT) {
                    const int bbi = r >> 11, s = r & (SS - 1);
                    const int h = cb >> 6, d = cb & 63;
                    *(float2*)(out + ((size_t)(bbi * HH + h) * SS + s) * DHH + d) = v;
                } else {
                    *(float2*)(out + (size_t)r * EE + cb) = v;
                }
            }
        }
    }
}

__global__ __launch_bounds__(256, 2) void proj_gemm_kernel(
    const float* __restrict__ X, const float* __restrict__ Wt,
    const float* __restrict__ bias, float* __restrict__ out)
{
    gemm_body<1>(X, Wt, bias, out);
}

__global__ __launch_bounds__(256, 2) void o_gemm_kernel(
    const float* __restrict__ bias, float* __restrict__ out)
{
    gemm_body<0>(g_attn, g_wt + (size_t)3 * EE * EE, bias, out);
}

// ---------------------------------------------------------------------------
// MMA flash attention (R11-validated: 64-key tiles, register softmax, occ 2).
// Output written tf32-rounded so o_gemm can skip conversion.
// ---------------------------------------------------------------------------
#define AQ(r, cc)  sm[(r) * 68 + (cc)]
#define AK(r, cc)  sm[8704 + (r) * 68 + (cc)]
#define AV(d, kk)  sm[13056 + (d) * 68 + (kk)]
#define AP(r, cc)  sm[17408 + (r) * 68 + (cc)]
#define AM(r)      sm[26112 + (r)]
#define AL(r)      sm[26240 + (r)]
#define ASC(r)     sm[26368 + (r)]
#define AMK(kk)    ((int*)(sm + 26496))[(kk)]
#define PMX(w, r)  sm[26560 + (w) * 128 + (r)]
#define PSM(w, r)  sm[27072 + (w) * 128 + (r)]
#define ATTN_SMEM  (27584 * 4)

__global__ __launch_bounds__(256, 2) void attn_mma_kernel(
    const int* __restrict__ mask, float* __restrict__ out)
{
    extern __shared__ float sm[];
    const int tid = threadIdx.x;
    const int wid = tid >> 5, lane = tid & 31;
    const int g = lane >> 2, t4 = lane & 3;
    const int wm = wid >> 2, wn = wid & 3;
    const int bb = blockIdx.z, hh = blockIdx.y;
    const int q0 = blockIdx.x * 128;

    const float* Q = g_q + ((size_t)(bb * HH + hh) * SS) * DHH;
    const float* K = g_k + ((size_t)(bb * HH + hh) * SS) * DHH;
    const float* V = g_v + ((size_t)(bb * HH + hh) * SS) * DHH;

    #pragma unroll
    for (int r = 0; r < 8; r++) {
        const int id = r * 256 + tid;
        const int row = id >> 4, c4 = id & 15;
        float4 v = *(const float4*)(Q + (size_t)(q0 + row) * DHH + c4 * 4);
        v.x = tf32r(v.x); v.y = tf32r(v.y); v.z = tf32r(v.z); v.w = tf32r(v.w);
        *(float4*)&AQ(row, c4 * 4) = v;
    }
    if (tid < 128) { AM(tid) = -1e30f; AL(tid) = 0.f; }

    float o[4][2][4];
    #pragma unroll
    for (int mi = 0; mi < 4; mi++)
        #pragma unroll
        for (int ni = 0; ni < 2; ni++)
            #pragma unroll
            for (int e = 0; e < 4; e++) o[mi][ni][e] = 0.f;
    __syncthreads();

    for (int kt = 0; kt < SS; kt += 64) {
        #pragma unroll
        for (int r = 0; r < 4; r++) {
            const int id = r * 256 + tid;
            const int key = id >> 4, c4 = id & 15;
            float4 kv = *(const float4*)(K + (size_t)(kt + key) * DHH + c4 * 4);
            kv.x = tf32r(kv.x); kv.y = tf32r(kv.y); kv.z = tf32r(kv.z); kv.w = tf32r(kv.w);
            *(float4*)&AK(key, c4 * 4) = kv;
            float4 vv = *(const float4*)(V + (size_t)(kt + key) * DHH + c4 * 4);
            AV(c4 * 4 + 0, key) = tf32r(vv.x);
            AV(c4 * 4 + 1, key) = tf32r(vv.y);
            AV(c4 * 4 + 2, key) = tf32r(vv.z);
            AV(c4 * 4 + 3, key) = tf32r(vv.w);
        }
        if (tid < 64) AMK(tid) = mask[bb * SS + kt + tid];
        __syncthreads();

        float c[4][2][4];
        #pragma unroll
        for (int mi = 0; mi < 4; mi++)
            #pragma unroll
            for (int ni = 0; ni < 2; ni++)
                #pragma unroll
                for (int e = 0; e < 4; e++) c[mi][ni][e] = 0.f;

        #pragma unroll
        for (int kk = 0; kk < 64; kk += 8) {
            float a[4][4], b[2][2];
            #pragma unroll
            for (int mi = 0; mi < 4; mi++) {
                const int row = wm * 64 + mi * 16;
                a[mi][0] = AQ(row + g, kk + t4);
                a[mi][1] = AQ(row + g + 8, kk + t4);
                a[mi][2] = AQ(row + g, kk + t4 + 4);
                a[mi][3] = AQ(row + g + 8, kk + t4 + 4);
            }
            #pragma unroll
            for (int ni = 0; ni < 2; ni++) {
                const int col = wn * 16 + ni * 8 + g;
                b[ni][0] = AK(col, kk + t4);
                b[ni][1] = AK(col, kk + t4 + 4);
            }
            #pragma unroll
            for (int mi = 0; mi < 4; mi++)
                #pragma unroll
                for (int ni = 0; ni < 2; ni++)
                    MMA_TF32(c[mi][ni], a[mi], b[ni]);
        }

        int mk[2][2];
        #pragma unroll
        for (int ni = 0; ni < 2; ni++) {
            const int cb = wn * 16 + ni * 8 + t4 * 2;
            mk[ni][0] = AMK(cb); mk[ni][1] = AMK(cb + 1);
        }
        float rm0[4], rm1[4];
        #pragma unroll
        for (int mi = 0; mi < 4; mi++) {
            float m0 = -1e30f, m1 = -1e30f;
            #pragma unroll
            for (int ni = 0; ni < 2; ni++) {
                float v0 = c[mi][ni][0] * 0.125f, v1 = c[mi][ni][1] * 0.125f;
                float v2 = c[mi][ni][2] * 0.125f, v3 = c[mi][ni][3] * 0.125f;
                if (mk[ni][0] == 0) { v0 = -1e9f; v2 = -1e9f; }
                if (mk[ni][1] == 0) { v1 = -1e9f; v3 = -1e9f; }
                c[mi][ni][0] = v0; c[mi][ni][1] = v1;
                c[mi][ni][2] = v2; c[mi][ni][3] = v3;
                m0 = fmaxf(m0, fmaxf(v0, v1));
                m1 = fmaxf(m1, fmaxf(v2, v3));
            }
            m0 = fmaxf(m0, __shfl_xor_sync(0xffffffffu, m0, 1));
            m0 = fmaxf(m0, __shfl_xor_sync(0xffffffffu, m0, 2));
            m1 = fmaxf(m1, __shfl_xor_sync(0xffffffffu, m1, 1));
            m1 = fmaxf(m1, __shfl_xor_sync(0xffffffffu, m1, 2));
            rm0[mi] = m0; rm1[mi] = m1;
        }
        if (t4 == 0) {
            #pragma unroll
            for (int mi = 0; mi < 4; mi++) {
                const int r0 = wm * 64 + mi * 16 + g;
                PMX(wn, r0) = rm0[mi];
                PMX(wn, r0 + 8) = rm1[mi];
            }
        }
        __syncthreads();

        if (tid < 128) {
            const float mt = fmaxf(fmaxf(PMX(0, tid), PMX(1, tid)),
                                   fmaxf(PMX(2, tid), PMX(3, tid)));
            const float mo = AM(tid);
            const float mn = fmaxf(mo, mt);
            AM(tid) = mn;
            ASC(tid) = __expf(mo - mn);
        }
        __syncthreads();

        #pragma unroll
        for (int mi = 0; mi < 4; mi++) {
            const int r0 = wm * 64 + mi * 16 + g;
            const float mn0 = AM(r0), mn1 = AM(r0 + 8);
            float s0 = 0.f, s1 = 0.f;
            #pragma unroll
            for (int ni = 0; ni < 2; ni++) {
                const int cb = wn * 16 + ni * 8 + t4 * 2;
                const float p0 = tf32r(__expf(c[mi][ni][0] - mn0));
                const float p1 = tf32r(__expf(c[mi][ni][1] - mn0));
                const float p2 = tf32r(__expf(c[mi][ni][2] - mn1));
                const float p3 = tf32r(__expf(c[mi][ni][3] - mn1));
                s0 += p0 + p1; s1 += p2 + p3;
                AP(r0, cb) = p0;     AP(r0, cb + 1) = p1;
                AP(r0 + 8, cb) = p2; AP(r0 + 8, cb + 1) = p3;
            }
            s0 += __shfl_xor_sync(0xffffffffu, s0, 1);
            s0 += __shfl_xor_sync(0xffffffffu, s0, 2);
            s1 += __shfl_xor_sync(0xffffffffu, s1, 1);
            s1 += __shfl_xor_sync(0xffffffffu, s1, 2);
            if (t4 == 0) { PSM(wn, r0) = s0; PSM(wn, r0 + 8) = s1; }
            const float sc0 = ASC(r0), sc1 = ASC(r0 + 8);
            #pragma unroll
            for (int ni = 0; ni < 2; ni++) {
                o[mi][ni][0] *= sc0; o[mi][ni][1] *= sc0;
                o[mi][ni][2] *= sc1; o[mi][ni][3] *= sc1;
            }
        }
        __syncthreads();

        if (tid < 128) {
            AL(tid) = AL(tid) * ASC(tid)
                    + PSM(0, tid) + PSM(1, tid) + PSM(2, tid) + PSM(3, tid);
        }

        #pragma unroll
        for (int kk = 0; kk < 64; kk += 8) {
            float a[4][4], b[2][2];
            #pragma unroll
            for (int mi = 0; mi < 4; mi++) {
                const int row = wm * 64 + mi * 16;
                a[mi][0] = AP(row + g, kk + t4);
                a[mi][1] = AP(row + g + 8, kk + t4);
                a[mi][2] = AP(row + g, kk + t4 + 4);
                a[mi][3] = AP(row + g + 8, kk + t4 + 4);
            }
            #pragma unroll
            for (int ni = 0; ni < 2; ni++) {
                const int col = wn * 16 + ni * 8 + g;
                b[ni][0] = AV(col, kk + t4);
                b[ni][1] = AV(col, kk + t4 + 4);
            }
            #pragma unroll
            for (int mi = 0; mi < 4; mi++)
                #pragma unroll
                for (int ni = 0; ni < 2; ni++)
                    MMA_TF32(o[mi][ni], a[mi], b[ni]);
        }
        __syncthreads();
    }

    #pragma unroll
    for (int mi = 0; mi < 4; mi++) {
        const int r0 = wm * 64 + mi * 16 + g;
        const float li0 = 1.0f / AL(r0), li1 = 1.0f / AL(r0 + 8);
        #pragma unroll
        for (int ni = 0; ni < 2; ni++) {
            const int cb = wn * 16 + ni * 8 + t4 * 2;
            float2 v;
            v.x = tf32r(o[mi][ni][0] * li0); v.y = tf32r(o[mi][ni][1] * li0);
            *(float2*)(out + (size_t)(bb * SS + q0 + r0) * EE + hh * DHH + cb) = v;
            v.x = tf32r(o[mi][ni][2] * li1); v.y = tf32r(o[mi][ni][3] * li1);
            *(float2*)(out + (size_t)(bb * SS + q0 + r0 + 8) * EE + hh * DHH + cb) = v;
        }
    }
}

// ---------------------------------------------------------------------------
extern "C" void kernel_launch(void* const* d_in, const int* in_sizes, int n_in,
                              void* d_out, int out_size)
{
    const float* query = (const float*)d_in[0];
    const float* key   = (const float*)d_in[1];
    const float* value = (const float*)d_in[2];
    const int*   mask  = (const int*)  d_in[3];
    const float* Wq = (const float*)d_in[4];
    const float* bq = (const float*)d_in[5];
    const float* Wk = (const float*)d_in[6];
    const float* bk = (const float*)d_in[7];
    const float* Wv = (const float*)d_in[8];
    const float* bv = (const float*)d_in[9];
    const float* Wo = (const float*)d_in[10];
    const float* bo = (const float*)d_in[11];
    float* out = (float*)d_out;

    float *gq, *gk, *gv, *ga, *gw, *gi;
    cudaGetSymbolAddress((void**)&gq, g_q);
    cudaGetSymbolAddress((void**)&gk, g_k);
    cudaGetSymbolAddress((void**)&gv, g_v);
    cudaGetSymbolAddress((void**)&ga, g_attn);
    cudaGetSymbolAddress((void**)&gw, g_wt);
    cudaGetSymbolAddress((void**)&gi, g_in);

    cudaFuncSetAttribute(attn_mma_kernel,
                         cudaFuncAttributeMaxDynamicSharedMemorySize, ATTN_SMEM);
    cudaFuncSetAttribute(proj_gemm_kernel,
                         cudaFuncAttributeMaxDynamicSharedMemorySize, GEMM_SMEM);
    cudaFuncSetAttribute(o_gemm_kernel,
                         cudaFuncAttributeMaxDynamicSharedMemorySize, GEMM_SMEM);

    dim3 rgrid((MM * EE) / (256 * 4), 3);
    round3_kernel<<<rgrid, 256>>>(query, key, value);

    dim3 tgrid(EE / 32, EE / 32, 4);
    dim3 tblk(32, 8);
    transpose4_kernel<<<tgrid, tblk>>>(Wq, Wk, Wv, Wo);

    dim3 ggrid(EE / 128, MM / 128);        // (8, 32) = 256 CTAs
    proj_gemm_kernel<<<ggrid, 256, GEMM_SMEM>>>(gi + 0 * (size_t)MM * EE, gw + 0 * (size_t)EE * EE, bq, gq);
    proj_gemm_kernel<<<ggrid, 256, GEMM_SMEM>>>(gi + 1 * (size_t)MM * EE, gw + 1 * (size_t)EE * EE, bk, gk);
    proj_gemm_kernel<<<ggrid, 256, GEMM_SMEM>>>(gi + 2 * (size_t)MM * EE, gw + 2 * (size_t)EE * EE, bv, gv);

    dim3 agrid(SS / 128, HH, BB);          // (16, 16, 2)
    attn_mma_kernel<<<agrid, 256, ATTN_SMEM>>>(mask, ga);

    o_gemm_kernel<<<ggrid, 256, GEMM_SMEM>>>(bo, out);
}